// round 13
// baseline (speedup 1.0000x reference)
#include <cuda_runtime.h>
#include <cuda_bf16.h>
#include <cstdint>
#include <math.h>

#define BATCH 8
#define CIN   512
#define HW    1024
#define DQKV  768
#define DVDIM 256
#define COUT  512

// ---------------- scratch (static device globals; allocation-free rule) ----
__device__ float g_attn[(size_t)BATCH * DVDIM * HW]; // 8 MB [b][c][s] (ref-reshape layout)

__device__ __nv_bfloat16 g_qt_hi[(size_t)BATCH * HW * DQKV];  // 12 MB [b][s][o] qkvT hi
__device__ __nv_bfloat16 g_qt_lo[(size_t)BATCH * HW * DQKV];  // 12 MB [b][s][o] qkvT lo
__device__ __nv_bfloat16 g_wqkv_hi[DQKV * CIN],  g_wqkv_lo[DQKV * CIN];
__device__ __nv_bfloat16 g_wattn_hi[COUT * DVDIM], g_wattn_lo[COUT * DVDIM];
__device__ __nv_bfloat16 g_xt_hi[(size_t)BATCH * HW * CIN],  g_xt_lo[(size_t)BATCH * HW * CIN];    // [b][s][c]
__device__ __nv_bfloat16 g_at_hi[(size_t)BATCH * HW * DVDIM], g_at_lo[(size_t)BATCH * HW * DVDIM]; // [b][s][c]

// ---------------- helpers ---------------------------------------------------
__device__ __forceinline__ uint32_t smem_u32(const void* p) {
    uint32_t a;
    asm("{ .reg .u64 t; cvta.to.shared.u64 t, %1; cvt.u32.u64 %0, t; }" : "=r"(a) : "l"(p));
    return a;
}

#define LDSM_X4(r0, r1, r2, r3, addr)                                           \
    asm volatile("ldmatrix.sync.aligned.m8n8.x4.shared.b16 {%0,%1,%2,%3}, [%4];"\
                 : "=r"(r0), "=r"(r1), "=r"(r2), "=r"(r3) : "r"(addr))
#define LDSM_X2(r0, r1, addr)                                                   \
    asm volatile("ldmatrix.sync.aligned.m8n8.x2.shared.b16 {%0,%1}, [%2];"      \
                 : "=r"(r0), "=r"(r1) : "r"(addr))
#define LDSM_X2T(r0, r1, addr)                                                  \
    asm volatile("ldmatrix.sync.aligned.m8n8.x2.trans.shared.b16 {%0,%1}, [%2];"\
                 : "=r"(r0), "=r"(r1) : "r"(addr))

#define CP_ASYNC16(dst, src)                                                    \
    asm volatile("cp.async.cg.shared.global [%0], [%1], 16;"                    \
                 :: "r"(dst), "l"(src))
#define CP_COMMIT() asm volatile("cp.async.commit_group;" ::: "memory")
#define CP_WAIT1()  asm volatile("cp.async.wait_group 1;" ::: "memory")
#define CP_WAIT0()  asm volatile("cp.async.wait_group 0;" ::: "memory")

__device__ __forceinline__ void mma_bf16(float* c, const uint32_t* a, const uint32_t* b) {
    asm volatile("mma.sync.aligned.m16n8k16.row.col.f32.bf16.bf16.f32 "
                 "{%0,%1,%2,%3}, {%4,%5,%6,%7}, {%8,%9}, {%0,%1,%2,%3};"
                 : "+f"(c[0]), "+f"(c[1]), "+f"(c[2]), "+f"(c[3])
                 : "r"(a[0]), "r"(a[1]), "r"(a[2]), "r"(a[3]), "r"(b[0]), "r"(b[1]));
}

// FMA-pipe exp (no MUFU), |rel err| ~ 3e-7. Logits are tiny (sigma~0.2).
__device__ __forceinline__ float fast_exp(float x) {
    const float t  = x * 1.442695041f;
    const float tm = t + 12582912.0f;
    const int   k  = __float_as_int(tm) - 0x4b400000;
    const float f  = t - (tm - 12582912.0f);
    float p = 1.33336498e-3f;
    p = fmaf(p, f, 9.81094252e-3f);
    p = fmaf(p, f, 5.55036691e-2f);
    p = fmaf(p, f, 2.40226597e-1f);
    p = fmaf(p, f, 6.93147182e-1f);
    p = fmaf(p, f, 1.0f);
    return __int_as_float(__float_as_int(p) + (k << 23));
}

// ---------------- conversion kernels ---------------------------------------
__global__ void split_kernel(const float* __restrict__ w,
                             __nv_bfloat16* __restrict__ hi,
                             __nv_bfloat16* __restrict__ lo, int n) {
    int i = blockIdx.x * 256 + threadIdx.x;
    if (i < n) {
        float v = w[i];
        __nv_bfloat16 h = __float2bfloat16(v);
        hi[i] = h;
        lo[i] = __float2bfloat16(v - __bfloat162float(h));
    }
}

// X[b][C][S] -> out[b][S][C] bf16 hi/lo (transpose + split)
__global__ void tsplit_kernel(const float* __restrict__ X,
                              __nv_bfloat16* __restrict__ hi,
                              __nv_bfloat16* __restrict__ lo, int C, int S) {
    __shared__ float t[32][33];
    const int b = blockIdx.z;
    const int c0 = blockIdx.y * 32, s0 = blockIdx.x * 32;
    const int tx = threadIdx.x, ty = threadIdx.y; // 32 x 8
    const float* Xb = X + (size_t)b * C * S;
    #pragma unroll
    for (int i = 0; i < 32; i += 8)
        t[ty + i][tx] = Xb[(size_t)(c0 + ty + i) * S + s0 + tx];
    __syncthreads();
    const size_t ob = (size_t)b * S * C;
    #pragma unroll
    for (int i = 0; i < 32; i += 8) {
        float v = t[tx][ty + i];
        __nv_bfloat16 h = __float2bfloat16(v);
        size_t idx = ob + (size_t)(s0 + ty + i) * C + c0 + tx;
        hi[idx] = h;
        lo[idx] = __float2bfloat16(v - __bfloat162float(h));
    }
}

// ---------------- HMMA split-bf16 GEMM, 64x128 tile, 3 CTAs/SM --------------
// 128 threads, 4 warps (2 m-bands x 2 n-bands), warp tile 32x64, BK=32 chunks,
// cp.async 2-stage. Rows padded to 40 bf16 (80 B) -> conflict-free ldmatrix.
#define ST_A    (64 * 80)           // 5120 B  (one 64x32 bf16 tile)
#define ST_Bt   (128 * 80)          // 10240 B (one 128x32 bf16 tile)
#define STAGE3  (2 * ST_A + 2 * ST_Bt)  // 30720 B
#define GM_SMEM (2 * STAGE3)            // 61440 B

template<int K, bool COLB, bool SPLITOUT>
__global__ __launch_bounds__(128) void gemm_mma(
    const __nv_bfloat16* __restrict__ Ahi_g, const __nv_bfloat16* __restrict__ Alo_g,
    const __nv_bfloat16* __restrict__ Bhi_g, const __nv_bfloat16* __restrict__ Blo_g,
    const float* __restrict__ bias, float* __restrict__ C_all,
    __nv_bfloat16* __restrict__ Chi_all, __nv_bfloat16* __restrict__ Clo_all,
    int M, int N, size_t aStride, size_t bStride, int scale_limit, float scale)
{
    extern __shared__ char smem[];
    const uint32_t sb = smem_u32(smem);

    const int tid  = threadIdx.x;
    const int wid  = tid >> 5;
    const int lane = tid & 31;
    const int wm = wid >> 1;          // 0..1 -> 32-row band
    const int wn = wid & 1;           // 0..1 -> 64-col band
    const int b  = blockIdx.z, m0 = blockIdx.y * 64, n0 = blockIdx.x * 128;

    const __nv_bfloat16* gsrc[4];
    gsrc[0] = Ahi_g + (size_t)b * aStride + (size_t)m0 * K;
    gsrc[1] = Alo_g + (size_t)b * aStride + (size_t)m0 * K;
    gsrc[2] = Bhi_g + (size_t)b * bStride + (size_t)n0 * K;
    gsrc[3] = Blo_g + (size_t)b * bStride + (size_t)n0 * K;

    const int a_row  = wm * 32 + (lane & 7) + ((lane >> 3) & 1) * 8; // + mt*16
    const int a_koff = ((lane >> 3) >> 1) * 8;
    const int b_row  = wn * 64 + (lane & 7);                          // + nt*8
    const int b_koff = ((lane >> 3) & 1) * 8;

    float acc[2][8][4] = {};
    constexpr int NCH = K / 32;

    // copy plan: 1536 16B-chunks/stage, 12 per thread.
    // grow 0..383: [0,64) Ahi, [64,128) Alo, [128,256) Bhi, [256,384) Blo.
    #pragma unroll
    for (int it = 0; it < 12; it++) {
        const int slot = it * 128 + tid;
        const int grow = slot >> 2, cg = slot & 3;
        const __nv_bfloat16* src;
        uint32_t soff;
        if (grow < 128) {
            const int r = grow & 63, hl = grow >> 6;
            src  = gsrc[hl] + (size_t)r * K + cg * 8;
            soff = (uint32_t)(hl * ST_A + r * 80 + cg * 16);
        } else {
            const int g2 = grow - 128, r = g2 & 127, hl = g2 >> 7;
            src  = gsrc[2 + hl] + (size_t)r * K + cg * 8;
            soff = (uint32_t)(2 * ST_A + hl * ST_Bt + r * 80 + cg * 16);
        }
        CP_ASYNC16(sb + soff, src);
    }
    CP_COMMIT();

    for (int ch = 0; ch < NCH; ch++) {
        if (ch + 1 < NCH) {
            const uint32_t dstb = sb + ((ch + 1) & 1) * STAGE3;
            const int c0k = (ch + 1) * 32;
            #pragma unroll
            for (int it = 0; it < 12; it++) {
                const int slot = it * 128 + tid;
                const int grow = slot >> 2, cg = slot & 3;
                const __nv_bfloat16* src;
                uint32_t soff;
                if (grow < 128) {
                    const int r = grow & 63, hl = grow >> 6;
                    src  = gsrc[hl] + (size_t)r * K + c0k + cg * 8;
                    soff = (uint32_t)(hl * ST_A + r * 80 + cg * 16);
                } else {
                    const int g2 = grow - 128, r = g2 & 127, hl = g2 >> 7;
                    src  = gsrc[2 + hl] + (size_t)r * K + c0k + cg * 8;
                    soff = (uint32_t)(2 * ST_A + hl * ST_Bt + r * 80 + cg * 16);
                }
                CP_ASYNC16(dstb + soff, src);
            }
            CP_COMMIT();
            CP_WAIT1();
        } else {
            CP_WAIT0();
        }
        __syncthreads();

        const uint32_t st = sb + (ch & 1) * STAGE3;
        const uint32_t sAhi_u = st, sAlo_u = st + ST_A;
        const uint32_t sBhi_u = st + 2 * ST_A, sBlo_u = st + 2 * ST_A + ST_Bt;

        #pragma unroll
        for (int ks = 0; ks < 2; ks++) {
            const int kb = ks * 16;
            uint32_t bh[8][2], bl[8][2];
            #pragma unroll
            for (int nt = 0; nt < 8; nt++) {
                const uint32_t off = (uint32_t)((b_row + nt * 8) * 80 +
                                                (kb + b_koff) * 2);
                LDSM_X2(bh[nt][0], bh[nt][1], sBhi_u + off);
                LDSM_X2(bl[nt][0], bl[nt][1], sBlo_u + off);
            }
            #pragma unroll
            for (int mt = 0; mt < 2; mt++) {
                const uint32_t off = (uint32_t)((a_row + mt * 16) * 80 +
                                                (kb + a_koff) * 2);
                uint32_t ah[4], al[4];
                LDSM_X4(ah[0], ah[1], ah[2], ah[3], sAhi_u + off);
                LDSM_X4(al[0], al[1], al[2], al[3], sAlo_u + off);
                #pragma unroll
                for (int nt = 0; nt < 8; nt++) {
                    mma_bf16(acc[mt][nt], ah, bh[nt]);
                    mma_bf16(acc[mt][nt], ah, bl[nt]);
                    mma_bf16(acc[mt][nt], al, bh[nt]);
                }
            }
        }
        __syncthreads();
    }

    const int col0 = n0 + wn * 64 + (lane & 3) * 2;
    #pragma unroll
    for (int mt = 0; mt < 2; mt++) {
        const int r0 = m0 + wm * 32 + mt * 16 + (lane >> 2);
        const int r1 = r0 + 8;
        if (COLB) {
            #pragma unroll
            for (int nt = 0; nt < 8; nt++) {
                const int cx = col0 + nt * 8, cy = cx + 1;
                const float bvx = bias[cx], bvy = bias[cy];
                const float scx = (cx < scale_limit) ? scale : 1.0f;
                const float scy = (cy < scale_limit) ? scale : 1.0f;
                const float v0x = (acc[mt][nt][0] + bvx) * scx;
                const float v0y = (acc[mt][nt][1] + bvy) * scy;
                const float v1x = (acc[mt][nt][2] + bvx) * scx;
                const float v1y = (acc[mt][nt][3] + bvy) * scy;
                if (SPLITOUT) {
                    __nv_bfloat16* Chi = Chi_all + (size_t)b * M * N;
                    __nv_bfloat16* Clo = Clo_all + (size_t)b * M * N;
                    __nv_bfloat162 h0 = __floats2bfloat162_rn(v0x, v0y);
                    __nv_bfloat162 l0 = __floats2bfloat162_rn(v0x - __bfloat162float(h0.x),
                                                              v0y - __bfloat162float(h0.y));
                    __nv_bfloat162 h1 = __floats2bfloat162_rn(v1x, v1y);
                    __nv_bfloat162 l1 = __floats2bfloat162_rn(v1x - __bfloat162float(h1.x),
                                                              v1y - __bfloat162float(h1.y));
                    *(__nv_bfloat162*)&Chi[(size_t)r0 * N + cx] = h0;
                    *(__nv_bfloat162*)&Clo[(size_t)r0 * N + cx] = l0;
                    *(__nv_bfloat162*)&Chi[(size_t)r1 * N + cx] = h1;
                    *(__nv_bfloat162*)&Clo[(size_t)r1 * N + cx] = l1;
                } else {
                    float* C = C_all + (size_t)b * M * N;
                    *(float2*)&C[(size_t)r0 * N + cx] = make_float2(v0x, v0y);
                    *(float2*)&C[(size_t)r1 * N + cx] = make_float2(v1x, v1y);
                }
            }
        } else {
            float* C = C_all + (size_t)b * M * N;
            const float bv0 = bias[r0], bv1 = bias[r1];
            const float sc0 = (r0 < scale_limit) ? scale : 1.0f;
            const float sc1 = (r1 < scale_limit) ? scale : 1.0f;
            #pragma unroll
            for (int nt = 0; nt < 8; nt++) {
                float2 v0, v1;
                v0.x = (acc[mt][nt][0] + bv0) * sc0;
                v0.y = (acc[mt][nt][1] + bv0) * sc0;
                v1.x = (acc[mt][nt][2] + bv1) * sc1;
                v1.y = (acc[mt][nt][3] + bv1) * sc1;
                *(float2*)&C[(size_t)r0 * N + col0 + nt * 8] = v0;
                *(float2*)&C[(size_t)r1 * N + col0 + nt * 8] = v1;
            }
        }
    }
}

// ---------------- HMMA fused attention (R10 version — best passing) ---------
#define AS_QHI 0
#define AS_QLO 33792
#define AS_KHI 67584
#define AS_KLO 84480
#define AS_VHI 101376
#define AS_VLO 118272
#define AS_WHI 135168
#define AS_WLO 176128
#define AS_TOTAL 217088

__global__ __launch_bounds__(256) void attn_mma_kernel(
    const __nv_bfloat16* __restrict__ qt_hi, const __nv_bfloat16* __restrict__ qt_lo,
    float* __restrict__ attn_out)
{
    extern __shared__ char sm[];
    const uint32_t sb = smem_u32(sm);
    const int tid = threadIdx.x, lane = tid & 31, wid = tid >> 5;
    const int wq = wid >> 1, w2 = wid & 1;
    const int qr0 = wq * 16;
    const int b = blockIdx.y, qbase = blockIdx.x * 64;
    const __nv_bfloat16* qth = qt_hi + (size_t)b * HW * DQKV;
    const __nv_bfloat16* qtl = qt_lo + (size_t)b * HW * DQKV;

    const int ar  = (lane & 7) + ((lane >> 3) & 1) * 8;
    const int ak  = ((lane >> 3) >> 1) * 8;
    const int br_ = (lane & 7);
    const int bk  = ((lane >> 3) & 1) * 8;

    // ---- prologue: Q + K0 (group 1), V0 (group 2) ----
    for (int i = tid; i < 2048; i += 256) {
        const int r = i >> 5, c = i & 31;
        const size_t so = (size_t)(qbase + r) * DQKV + c * 8;
        CP_ASYNC16(sb + AS_QHI + r * 528 + c * 16, qth + so);
        CP_ASYNC16(sb + AS_QLO + r * 528 + c * 16, qtl + so);
    }
    for (int i = tid; i < 1024; i += 256) {
        const int r = i >> 5, c = i & 31;
        const size_t so = (size_t)r * DQKV + 256 + c * 8;
        CP_ASYNC16(sb + AS_KHI + r * 528 + c * 16, qth + so);
        CP_ASYNC16(sb + AS_KLO + r * 528 + c * 16, qtl + so);
    }
    CP_COMMIT();
    for (int i = tid; i < 1024; i += 256) {
        const int r = i >> 5, c = i & 31;
        const size_t so = (size_t)r * DQKV + 512 + c * 8;
        CP_ASYNC16(sb + AS_VHI + r * 528 + c * 16, qth + so);
        CP_ASYNC16(sb + AS_VLO + r * 528 + c * 16, qtl + so);
    }
    CP_COMMIT();

    float acc[4][4][4] = {};

    for (int it = 0; it < 32; it++) {
        CP_WAIT1();           // K_it (and Q) arrived; V_it may be in flight
        __syncthreads();

        // ---- logits: warp tile 16q x 16k (k-half w2), all 8 heads ----
        float lg[8][2][4] = {};
        #pragma unroll
        for (int h = 0; h < 8; h++) {
            #pragma unroll
            for (int ks = 0; ks < 2; ks++) {
                const int dco = h * 32 + ks * 16;
                uint32_t aH[4], aL[4];
                const uint32_t aoff = (uint32_t)((qr0 + ar) * 528 + (dco + ak) * 2);
                LDSM_X4(aH[0], aH[1], aH[2], aH[3], sb + AS_QHI + aoff);
                LDSM_X4(aL[0], aL[1], aL[2], aL[3], sb + AS_QLO + aoff);
                #pragma unroll
                for (int t = 0; t < 2; t++) {
                    uint32_t bH[2], bL[2];
                    const uint32_t boff = (uint32_t)((w2 * 16 + t * 8 + br_) * 528 +
                                                     (dco + bk) * 2);
                    LDSM_X2(bH[0], bH[1], sb + AS_KHI + boff);
                    LDSM_X2(bL[0], bL[1], sb + AS_KLO + boff);
                    mma_bf16(lg[h][t], aH, bH);
                    mma_bf16(lg[h][t], aH, bL);
                    mma_bf16(lg[h][t], aL, bH);
                }
            }
        }
        __syncthreads();      // all warps done reading K_it

        // prefetch K_{it+1} into the (now free) K buffer
        if (it < 31) {
            const int kt = (it + 1) * 32;
            for (int i = tid; i < 1024; i += 256) {
                const int r = i >> 5, c = i & 31;
                const size_t so = (size_t)(kt + r) * DQKV + 256 + c * 8;
                CP_ASYNC16(sb + AS_KHI + r * 528 + c * 16, qth + so);
                CP_ASYNC16(sb + AS_KLO + r * 528 + c * 16, qtl + so);
            }
            CP_COMMIT();
        }

        // ---- head-softmax (thread-local) + weight store (bf16 hi/lo) ----
        #pragma unroll
        for (int t = 0; t < 2; t++) {
            #pragma unroll
            for (int p = 0; p < 2; p++) {
                float e0[8], e1[8];
                float s0 = 0.0f, s1 = 0.0f;
                #pragma unroll
                for (int h = 0; h < 8; h++) {
                    e0[h] = fast_exp(lg[h][t][p ? 2 : 0]);
                    e1[h] = fast_exp(lg[h][t][p ? 3 : 1]);
                    s0 += e0[h]; s1 += e1[h];
                }
                const float i0 = 1.0f / s0, i1 = 1.0f / s1;
                const int q = qr0 + (lane >> 2) + p * 8;
                const int k = w2 * 16 + t * 8 + (lane & 3) * 2;
                #pragma unroll
                for (int h = 0; h < 8; h++) {
                    const float wa = e0[h] * i0, wb = e1[h] * i1;
                    __nv_bfloat162 hh = __floats2bfloat162_rn(wa, wb);
                    __nv_bfloat162 ll = __floats2bfloat162_rn(wa - __bfloat162float(hh.x),
                                                              wb - __bfloat162float(hh.y));
                    const uint32_t off = (uint32_t)((h * 64 + q) * 80 + k * 2);
                    *(__nv_bfloat162*)(sm + AS_WHI + off) = hh;
                    *(__nv_bfloat162*)(sm + AS_WLO + off) = ll;
                }
            }
        }
        if (it < 31) { CP_WAIT1(); } else { CP_WAIT0(); }   // V_it arrived
        __syncthreads();                                    // W visible

        // ---- AV: warp owns 16q x 128d (heads w2*4..+3); V via ldmatrix.trans
        #pragma unroll
        for (int h4 = 0; h4 < 4; h4++) {
            const int habs = w2 * 4 + h4;
            #pragma unroll
            for (int ks = 0; ks < 2; ks++) {
                uint32_t wH[4], wL[4];
                const uint32_t aoff = (uint32_t)((habs * 64 + qr0 + ar) * 80 +
                                                 (ks * 16 + ak) * 2);
                LDSM_X4(wH[0], wH[1], wH[2], wH[3], sb + AS_WHI + aoff);
                LDSM_X4(wL[0], wL[1], wL[2], wL[3], sb + AS_WLO + aoff);
                #pragma unroll
                for (int nt = 0; nt < 4; nt++) {
                    uint32_t vH[2], vL[2];
                    const uint32_t boff = (uint32_t)((ks * 16 + ar) * 528 +
                                                     (habs * 32 + nt * 8) * 2);
                    LDSM_X2T(vH[0], vH[1], sb + AS_VHI + boff);
                    LDSM_X2T(vL[0], vL[1], sb + AS_VLO + boff);
                    mma_bf16(acc[h4][nt], wH, vH);
                    mma_bf16(acc[h4][nt], wH, vL);
                    mma_bf16(acc[h4][nt], wL, vH);
                }
            }
        }
        __syncthreads();      // V_it and W consumed

        // prefetch V_{it+1}
        if (it < 31) {
            const int kt = (it + 1) * 32;
            for (int i = tid; i < 1024; i += 256) {
                const int r = i >> 5, c = i & 31;
                const size_t so = (size_t)(kt + r) * DQKV + 512 + c * 8;
                CP_ASYNC16(sb + AS_VHI + r * 528 + c * 16, qth + so);
                CP_ASYNC16(sb + AS_VLO + r * 528 + c * 16, qtl + so);
            }
            CP_COMMIT();
        }
    }

    // ---- epilogue: reference-reshape layout ----
    float* ab = attn_out + (size_t)b * DVDIM * HW;
    #pragma unroll
    for (int h4 = 0; h4 < 4; h4++) {
        const int habs = w2 * 4 + h4;
        #pragma unroll
        for (int nt = 0; nt < 4; nt++) {
            const int q0g = qbase + qr0 + (lane >> 2);
            const int q1g = q0g + 8;
            const int d   = nt * 8 + (lane & 3) * 2;
            const int ch0 = habs * 32 + (q0g >> 5), sp0 = (q0g & 31) * 32 + d;
            const int ch1 = habs * 32 + (q1g >> 5), sp1 = (q1g & 31) * 32 + d;
            *(float2*)&ab[(size_t)ch0 * HW + sp0] = make_float2(acc[h4][nt][0], acc[h4][nt][1]);
            *(float2*)&ab[(size_t)ch1 * HW + sp1] = make_float2(acc[h4][nt][2], acc[h4][nt][3]);
        }
    }
}

// ---------------------------------------------------------------------------
extern "C" void kernel_launch(void* const* d_in, const int* in_sizes, int n_in,
                              void* d_out, int out_size)
{
    const float* x      = (const float*)d_in[0];
    const float* w_qkv  = (const float*)d_in[1];
    const float* b_qkv  = (const float*)d_in[2];
    const float* w_attn = (const float*)d_in[3];
    const float* b_attn = (const float*)d_in[4];
    float* out = (float*)d_out;

    float* attn; cudaGetSymbolAddress((void**)&attn, g_attn);
    __nv_bfloat16 *qth, *qtl, *wqh, *wql, *wah, *wal, *xth, *xtl, *ath, *atl;
    cudaGetSymbolAddress((void**)&qth, g_qt_hi);
    cudaGetSymbolAddress((void**)&qtl, g_qt_lo);
    cudaGetSymbolAddress((void**)&wqh, g_wqkv_hi);
    cudaGetSymbolAddress((void**)&wql, g_wqkv_lo);
    cudaGetSymbolAddress((void**)&wah, g_wattn_hi);
    cudaGetSymbolAddress((void**)&wal, g_wattn_lo);
    cudaGetSymbolAddress((void**)&xth, g_xt_hi);
    cudaGetSymbolAddress((void**)&xtl, g_xt_lo);
    cudaGetSymbolAddress((void**)&ath, g_at_hi);
    cudaGetSymbolAddress((void**)&atl, g_at_lo);

    cudaFuncSetAttribute(gemm_mma<CIN, true, true>,
                         cudaFuncAttributeMaxDynamicSharedMemorySize, GM_SMEM);
    cudaFuncSetAttribute(gemm_mma<DVDIM, false, false>,
                         cudaFuncAttributeMaxDynamicSharedMemorySize, GM_SMEM);
    cudaFuncSetAttribute(attn_mma_kernel,
                         cudaFuncAttributeMaxDynamicSharedMemorySize, AS_TOTAL);

    // 0) precision-split weights; transpose+split x
    split_kernel<<<(DQKV * CIN + 255) / 256, 256>>>(w_qkv, wqh, wql, DQKV * CIN);
    split_kernel<<<(COUT * DVDIM + 255) / 256, 256>>>(w_attn, wah, wal, COUT * DVDIM);
    {
        dim3 grid(HW / 32, CIN / 32, BATCH);
        tsplit_kernel<<<grid, dim3(32, 8)>>>(x, xth, xtl, CIN, HW);
    }

    // 1) QKV projection TRANSPOSED, bf16 hi/lo output (+colbias, Q cols scaled)
    {
        dim3 grid(DQKV / 128, HW / 64, BATCH); // (6, 16, 8) = 768 CTAs
        gemm_mma<CIN, true, true><<<grid, 128, GM_SMEM>>>(
            xth, xtl, wqh, wql, b_qkv, nullptr, qth, qtl,
            HW, DQKV, (size_t)HW * CIN, 0, 256, 0.17677669529663687f);
    }

    // 2) fused HMMA attention (head-axis softmax) -> g_attn (ref-reshape fp32)
    {
        dim3 grid(HW / 64, BATCH); // (16, 8)
        attn_mma_kernel<<<grid, 256, AS_TOTAL>>>(qth, qtl, attn);
    }

    // 2.5) transpose+split attention output for GEMM3's B operand
    {
        dim3 grid(HW / 32, DVDIM / 32, BATCH);
        tsplit_kernel<<<grid, dim3(32, 8)>>>(attn, ath, atl, DVDIM, HW);
    }

    // 3) output projection (+row bias, fp32 out)
    {
        dim3 grid(HW / 128, COUT / 64, BATCH); // (8, 8, 8) = 512 CTAs
        gemm_mma<DVDIM, false, false><<<grid, 128, GM_SMEM>>>(
            wah, wal, ath, atl, b_attn, out, nullptr, nullptr,
            COUT, HW, 0, (size_t)HW * DVDIM, 0, 1.0f);
    }
}

// round 14
// speedup vs baseline: 1.0488x; 1.0488x over previous
#include <cuda_runtime.h>
#include <cuda_bf16.h>
#include <cstdint>
#include <math.h>

#define BATCH 8
#define CIN   512
#define HW    1024
#define DQKV  768
#define DVDIM 256
#define COUT  512

// ---------------- scratch (static device globals; allocation-free rule) ----
__device__ __nv_bfloat16 g_qt_hi[(size_t)BATCH * HW * DQKV];  // 12 MB [b][s][o] qkvT hi
__device__ __nv_bfloat16 g_qt_lo[(size_t)BATCH * HW * DQKV];  // 12 MB [b][s][o] qkvT lo
__device__ __nv_bfloat16 g_wqkv_hi[DQKV * CIN],  g_wqkv_lo[DQKV * CIN];
__device__ __nv_bfloat16 g_wattn_hi[COUT * DVDIM], g_wattn_lo[COUT * DVDIM];
__device__ __nv_bfloat16 g_xt_hi[(size_t)BATCH * HW * CIN],  g_xt_lo[(size_t)BATCH * HW * CIN];    // [b][s][c]
__device__ __nv_bfloat16 g_at_hi[(size_t)BATCH * DVDIM * HW], g_at_lo[(size_t)BATCH * DVDIM * HW]; // [b][c][s] ref-reshape

// ---------------- helpers ---------------------------------------------------
__device__ __forceinline__ uint32_t smem_u32(const void* p) {
    uint32_t a;
    asm("{ .reg .u64 t; cvta.to.shared.u64 t, %1; cvt.u32.u64 %0, t; }" : "=r"(a) : "l"(p));
    return a;
}

#define LDSM_X4(r0, r1, r2, r3, addr)                                           \
    asm volatile("ldmatrix.sync.aligned.m8n8.x4.shared.b16 {%0,%1,%2,%3}, [%4];"\
                 : "=r"(r0), "=r"(r1), "=r"(r2), "=r"(r3) : "r"(addr))
#define LDSM_X2(r0, r1, addr)                                                   \
    asm volatile("ldmatrix.sync.aligned.m8n8.x2.shared.b16 {%0,%1}, [%2];"      \
                 : "=r"(r0), "=r"(r1) : "r"(addr))
#define LDSM_X2T(r0, r1, addr)                                                  \
    asm volatile("ldmatrix.sync.aligned.m8n8.x2.trans.shared.b16 {%0,%1}, [%2];"\
                 : "=r"(r0), "=r"(r1) : "r"(addr))

#define CP_ASYNC16(dst, src)                                                    \
    asm volatile("cp.async.cg.shared.global [%0], [%1], 16;"                    \
                 :: "r"(dst), "l"(src))
#define CP_COMMIT() asm volatile("cp.async.commit_group;" ::: "memory")
#define CP_WAIT1()  asm volatile("cp.async.wait_group 1;" ::: "memory")
#define CP_WAIT0()  asm volatile("cp.async.wait_group 0;" ::: "memory")

__device__ __forceinline__ void mma_bf16(float* c, const uint32_t* a, const uint32_t* b) {
    asm volatile("mma.sync.aligned.m16n8k16.row.col.f32.bf16.bf16.f32 "
                 "{%0,%1,%2,%3}, {%4,%5,%6,%7}, {%8,%9}, {%0,%1,%2,%3};"
                 : "+f"(c[0]), "+f"(c[1]), "+f"(c[2]), "+f"(c[3])
                 : "r"(a[0]), "r"(a[1]), "r"(a[2]), "r"(a[3]), "r"(b[0]), "r"(b[1]));
}

// FMA-pipe exp (no MUFU), |rel err| ~ 3e-7. Logits are tiny (sigma~0.2).
__device__ __forceinline__ float fast_exp(float x) {
    const float t  = x * 1.442695041f;
    const float tm = t + 12582912.0f;
    const int   k  = __float_as_int(tm) - 0x4b400000;
    const float f  = t - (tm - 12582912.0f);
    float p = 1.33336498e-3f;
    p = fmaf(p, f, 9.81094252e-3f);
    p = fmaf(p, f, 5.55036691e-2f);
    p = fmaf(p, f, 2.40226597e-1f);
    p = fmaf(p, f, 6.93147182e-1f);
    p = fmaf(p, f, 1.0f);
    return __int_as_float(__float_as_int(p) + (k << 23));
}

// ---------------- conversion kernels ---------------------------------------
__global__ void split_kernel(const float* __restrict__ w,
                             __nv_bfloat16* __restrict__ hi,
                             __nv_bfloat16* __restrict__ lo, int n) {
    int i = blockIdx.x * 256 + threadIdx.x;
    if (i < n) {
        float v = w[i];
        __nv_bfloat16 h = __float2bfloat16(v);
        hi[i] = h;
        lo[i] = __float2bfloat16(v - __bfloat162float(h));
    }
}

// X[b][C][S] -> out[b][S][C] bf16 hi/lo (transpose + split)
__global__ void tsplit_kernel(const float* __restrict__ X,
                              __nv_bfloat16* __restrict__ hi,
                              __nv_bfloat16* __restrict__ lo, int C, int S) {
    __shared__ float t[32][33];
    const int b = blockIdx.z;
    const int c0 = blockIdx.y * 32, s0 = blockIdx.x * 32;
    const int tx = threadIdx.x, ty = threadIdx.y; // 32 x 8
    const float* Xb = X + (size_t)b * C * S;
    #pragma unroll
    for (int i = 0; i < 32; i += 8)
        t[ty + i][tx] = Xb[(size_t)(c0 + ty + i) * S + s0 + tx];
    __syncthreads();
    const size_t ob = (size_t)b * S * C;
    #pragma unroll
    for (int i = 0; i < 32; i += 8) {
        float v = t[tx][ty + i];
        __nv_bfloat16 h = __float2bfloat16(v);
        size_t idx = ob + (size_t)(s0 + ty + i) * C + c0 + tx;
        hi[idx] = h;
        lo[idx] = __float2bfloat16(v - __bfloat162float(h));
    }
}

// ---------------- HMMA split-bf16 GEMM (R10 config: 128x128, 256t) ----------
#define BK2    32
#define RPAD2  40
#define TILE2  (128 * RPAD2 * 2)   // 10240 B
#define STAGE2 (4 * TILE2)         // 40960 B
#define GM_SMEM (2 * STAGE2)       // 81920 B

template<int K, bool COLB, bool SPLITOUT>
__global__ __launch_bounds__(256) void gemm_mma(
    const __nv_bfloat16* __restrict__ Ahi_g, const __nv_bfloat16* __restrict__ Alo_g,
    const __nv_bfloat16* __restrict__ Bhi_g, const __nv_bfloat16* __restrict__ Blo_g,
    const float* __restrict__ bias, float* __restrict__ C_all,
    __nv_bfloat16* __restrict__ Chi_all, __nv_bfloat16* __restrict__ Clo_all,
    int M, int N, size_t aStride, size_t bStride, int scale_limit, float scale)
{
    extern __shared__ char smem[];
    const uint32_t sb = smem_u32(smem);

    const int tid  = threadIdx.x;
    const int wid  = tid >> 5;
    const int lane = tid & 31;
    const int wm = wid >> 2;
    const int wn = wid & 3;
    const int b  = blockIdx.z, m0 = blockIdx.y * 128, n0 = blockIdx.x * 128;

    const __nv_bfloat16* gsrc[4];
    gsrc[0] = Ahi_g + (size_t)b * aStride + (size_t)m0 * K;
    gsrc[1] = Alo_g + (size_t)b * aStride + (size_t)m0 * K;
    gsrc[2] = Bhi_g + (size_t)b * bStride + (size_t)n0 * K;
    gsrc[3] = Blo_g + (size_t)b * bStride + (size_t)n0 * K;

    const int a_row  = wm * 64 + (lane & 7) + ((lane >> 3) & 1) * 8;
    const int a_koff = ((lane >> 3) >> 1) * 8;
    const int b_row  = wn * 32 + (lane & 7);
    const int b_koff = ((lane >> 3) & 1) * 8;

    float acc[4][4][4] = {};
    constexpr int NCH = K / BK2;

    #pragma unroll
    for (int it = 0; it < 8; it++) {
        const int slot = it * 256 + tid;
        const int t  = slot >> 9;
        const int in_ = slot & 511;
        const int r  = in_ >> 2;
        const int cg = in_ & 3;
        CP_ASYNC16(sb + t * TILE2 + r * (RPAD2 * 2) + cg * 16,
                   gsrc[t] + (size_t)r * K + cg * 8);
    }
    CP_COMMIT();

    for (int ch = 0; ch < NCH; ch++) {
        if (ch + 1 < NCH) {
            const uint32_t dstb = sb + ((ch + 1) & 1) * STAGE2;
            const int c0k = (ch + 1) * BK2;
            #pragma unroll
            for (int it = 0; it < 8; it++) {
                const int slot = it * 256 + tid;
                const int t  = slot >> 9;
                const int in_ = slot & 511;
                const int r  = in_ >> 2;
                const int cg = in_ & 3;
                CP_ASYNC16(dstb + t * TILE2 + r * (RPAD2 * 2) + cg * 16,
                           gsrc[t] + (size_t)r * K + c0k + cg * 8);
            }
            CP_COMMIT();
            CP_WAIT1();
        } else {
            CP_WAIT0();
        }
        __syncthreads();

        const uint32_t st = sb + (ch & 1) * STAGE2;
        const uint32_t sAhi_u = st, sAlo_u = st + TILE2;
        const uint32_t sBhi_u = st + 2 * TILE2, sBlo_u = st + 3 * TILE2;

        #pragma unroll
        for (int ks = 0; ks < BK2 / 16; ks++) {
            const int kb = ks * 16;
            uint32_t bh[4][2], bl[4][2];
            #pragma unroll
            for (int nt = 0; nt < 4; nt++) {
                const uint32_t off = (uint32_t)((b_row + nt * 8) * (RPAD2 * 2) +
                                                (kb + b_koff) * 2);
                LDSM_X2(bh[nt][0], bh[nt][1], sBhi_u + off);
                LDSM_X2(bl[nt][0], bl[nt][1], sBlo_u + off);
            }
            #pragma unroll
            for (int mt = 0; mt < 4; mt++) {
                const uint32_t off = (uint32_t)((a_row + mt * 16) * (RPAD2 * 2) +
                                                (kb + a_koff) * 2);
                uint32_t ah[4], al[4];
                LDSM_X4(ah[0], ah[1], ah[2], ah[3], sAhi_u + off);
                LDSM_X4(al[0], al[1], al[2], al[3], sAlo_u + off);
                #pragma unroll
                for (int nt = 0; nt < 4; nt++) {
                    mma_bf16(acc[mt][nt], ah, bh[nt]);
                    mma_bf16(acc[mt][nt], ah, bl[nt]);
                    mma_bf16(acc[mt][nt], al, bh[nt]);
                }
            }
        }
        __syncthreads();
    }

    const int col0 = n0 + wn * 32 + (lane & 3) * 2;
    #pragma unroll
    for (int mt = 0; mt < 4; mt++) {
        const int r0 = m0 + wm * 64 + mt * 16 + (lane >> 2);
        const int r1 = r0 + 8;
        if (COLB) {
            #pragma unroll
            for (int nt = 0; nt < 4; nt++) {
                const int cx = col0 + nt * 8, cy = cx + 1;
                const float bvx = bias[cx], bvy = bias[cy];
                const float scx = (cx < scale_limit) ? scale : 1.0f;
                const float scy = (cy < scale_limit) ? scale : 1.0f;
                const float v0x = (acc[mt][nt][0] + bvx) * scx;
                const float v0y = (acc[mt][nt][1] + bvy) * scy;
                const float v1x = (acc[mt][nt][2] + bvx) * scx;
                const float v1y = (acc[mt][nt][3] + bvy) * scy;
                if (SPLITOUT) {
                    __nv_bfloat16* Chi = Chi_all + (size_t)b * M * N;
                    __nv_bfloat16* Clo = Clo_all + (size_t)b * M * N;
                    __nv_bfloat162 h0 = __floats2bfloat162_rn(v0x, v0y);
                    __nv_bfloat162 l0 = __floats2bfloat162_rn(v0x - __bfloat162float(h0.x),
                                                              v0y - __bfloat162float(h0.y));
                    __nv_bfloat162 h1 = __floats2bfloat162_rn(v1x, v1y);
                    __nv_bfloat162 l1 = __floats2bfloat162_rn(v1x - __bfloat162float(h1.x),
                                                              v1y - __bfloat162float(h1.y));
                    *(__nv_bfloat162*)&Chi[(size_t)r0 * N + cx] = h0;
                    *(__nv_bfloat162*)&Clo[(size_t)r0 * N + cx] = l0;
                    *(__nv_bfloat162*)&Chi[(size_t)r1 * N + cx] = h1;
                    *(__nv_bfloat162*)&Clo[(size_t)r1 * N + cx] = l1;
                } else {
                    float* C = C_all + (size_t)b * M * N;
                    *(float2*)&C[(size_t)r0 * N + cx] = make_float2(v0x, v0y);
                    *(float2*)&C[(size_t)r1 * N + cx] = make_float2(v1x, v1y);
                }
            }
        } else {
            float* C = C_all + (size_t)b * M * N;
            const float bv0 = bias[r0], bv1 = bias[r1];
            const float sc0 = (r0 < scale_limit) ? scale : 1.0f;
            const float sc1 = (r1 < scale_limit) ? scale : 1.0f;
            #pragma unroll
            for (int nt = 0; nt < 4; nt++) {
                float2 v0, v1;
                v0.x = (acc[mt][nt][0] + bv0) * sc0;
                v0.y = (acc[mt][nt][1] + bv0) * sc0;
                v1.x = (acc[mt][nt][2] + bv1) * sc1;
                v1.y = (acc[mt][nt][3] + bv1) * sc1;
                *(float2*)&C[(size_t)r0 * N + col0 + nt * 8] = v0;
                *(float2*)&C[(size_t)r1 * N + col0 + nt * 8] = v1;
            }
        }
    }
}

// ---------------- GEMM3: B in [k][n] layout (trans ldmatrix), row bias ------
// out[b][o][s] = sum_c Wattn[o][c] * attn[c][s] + bias[o]
// A = Wattn K-major (shared across batch). B = attn [c][s] bf16 hi/lo.
// 128x128 tile, 256 threads, 8 warps (2x4), BK=32, cp.async 2-stage.
// B smem rows: 32 k-rows x 272 B (256 + 16 pad) -> trans-ldmatrix bank walk
// 68i mod 32 = 4i -> conflict-free (same pattern as attention V, validated).
#define G3_SA   (128 * 80)          // 10240 B per A tile
#define G3_SB   (32 * 272)          // 8704 B per B tile
#define G3_STAGE (2 * G3_SA + 2 * G3_SB)   // 37888 B
#define G3_SMEM  (2 * G3_STAGE)            // 75776 B

__global__ __launch_bounds__(256) void gemm3_bt(
    const __nv_bfloat16* __restrict__ Ahi_g, const __nv_bfloat16* __restrict__ Alo_g,
    const __nv_bfloat16* __restrict__ Bhi_g, const __nv_bfloat16* __restrict__ Blo_g,
    const float* __restrict__ bias, float* __restrict__ C_all)
{
    constexpr int K = DVDIM;     // 256
    constexpr int N = HW;        // 1024
    constexpr int M = COUT;      // 512
    extern __shared__ char smem[];
    const uint32_t sb = smem_u32(smem);

    const int tid  = threadIdx.x;
    const int wid  = tid >> 5;
    const int lane = tid & 31;
    const int wm = wid >> 2;      // 0..1 -> 64-row band
    const int wn = wid & 3;       // 0..3 -> 32-col band
    const int b  = blockIdx.z, m0 = blockIdx.y * 128, n0 = blockIdx.x * 128;

    const __nv_bfloat16* Ahi = Ahi_g + (size_t)m0 * K;
    const __nv_bfloat16* Alo = Alo_g + (size_t)m0 * K;
    const __nv_bfloat16* Bhi = Bhi_g + (size_t)b * K * N + n0;
    const __nv_bfloat16* Blo = Blo_g + (size_t)b * K * N + n0;
    float* C = C_all + (size_t)b * M * N;

    const int a_row  = wm * 64 + (lane & 7) + ((lane >> 3) & 1) * 8;
    const int a_koff = ((lane >> 3) >> 1) * 8;
    const int tb_row = (lane & 7) + ((lane >> 3) & 1) * 8;   // trans-B k-row within 16

    float acc[4][4][4] = {};
    constexpr int NCH = K / 32;   // 8

    // copy plan: 2048 chunks/stage (A hi/lo 512 each, B hi/lo 512 each)
    #pragma unroll
    for (int it = 0; it < 8; it++) {
        const int slot = it * 256 + tid;
        if (slot < 1024) {        // A
            const int hl = slot >> 9, in_ = slot & 511;
            const int r = in_ >> 2, cg = in_ & 3;
            CP_ASYNC16(sb + hl * G3_SA + r * 80 + cg * 16,
                       (hl ? Alo : Ahi) + (size_t)r * K + cg * 8);
        } else {                  // B
            const int s2 = slot - 1024;
            const int hl = s2 >> 9, in_ = s2 & 511;
            const int r = in_ >> 4, cg = in_ & 15;
            CP_ASYNC16(sb + 2 * G3_SA + hl * G3_SB + r * 272 + cg * 16,
                       (hl ? Blo : Bhi) + (size_t)r * N + cg * 8);
        }
    }
    CP_COMMIT();

    for (int ch = 0; ch < NCH; ch++) {
        if (ch + 1 < NCH) {
            const uint32_t dstb = sb + ((ch + 1) & 1) * G3_STAGE;
            const int c0k = (ch + 1) * 32;
            #pragma unroll
            for (int it = 0; it < 8; it++) {
                const int slot = it * 256 + tid;
                if (slot < 1024) {
                    const int hl = slot >> 9, in_ = slot & 511;
                    const int r = in_ >> 2, cg = in_ & 3;
                    CP_ASYNC16(dstb + hl * G3_SA + r * 80 + cg * 16,
                               (hl ? Alo : Ahi) + (size_t)r * K + c0k + cg * 8);
                } else {
                    const int s2 = slot - 1024;
                    const int hl = s2 >> 9, in_ = s2 & 511;
                    const int r = in_ >> 4, cg = in_ & 15;
                    CP_ASYNC16(dstb + 2 * G3_SA + hl * G3_SB + r * 272 + cg * 16,
                               (hl ? Blo : Bhi) + (size_t)(c0k + r) * N + cg * 8);
                }
            }
            CP_COMMIT();
            CP_WAIT1();
        } else {
            CP_WAIT0();
        }
        __syncthreads();

        const uint32_t st = sb + (ch & 1) * G3_STAGE;
        const uint32_t sAhi_u = st, sAlo_u = st + G3_SA;
        const uint32_t sBhi_u = st + 2 * G3_SA, sBlo_u = st + 2 * G3_SA + G3_SB;

        #pragma unroll
        for (int ks = 0; ks < 2; ks++) {
            const int kb = ks * 16;
            uint32_t bh[4][2], bl[4][2];
            #pragma unroll
            for (int nt = 0; nt < 4; nt++) {
                const uint32_t off = (uint32_t)((kb + tb_row) * 272 +
                                                (wn * 32 + nt * 8) * 2);
                LDSM_X2T(bh[nt][0], bh[nt][1], sBhi_u + off);
                LDSM_X2T(bl[nt][0], bl[nt][1], sBlo_u + off);
            }
            #pragma unroll
            for (int mt = 0; mt < 4; mt++) {
                const uint32_t off = (uint32_t)((a_row + mt * 16) * 80 +
                                                (kb + a_koff) * 2);
                uint32_t ah[4], al[4];
                LDSM_X4(ah[0], ah[1], ah[2], ah[3], sAhi_u + off);
                LDSM_X4(al[0], al[1], al[2], al[3], sAlo_u + off);
                #pragma unroll
                for (int nt = 0; nt < 4; nt++) {
                    mma_bf16(acc[mt][nt], ah, bh[nt]);
                    mma_bf16(acc[mt][nt], ah, bl[nt]);
                    mma_bf16(acc[mt][nt], al, bh[nt]);
                }
            }
        }
        __syncthreads();
    }

    const int col0 = n0 + wn * 32 + (lane & 3) * 2;
    #pragma unroll
    for (int mt = 0; mt < 4; mt++) {
        const int r0 = m0 + wm * 64 + mt * 16 + (lane >> 2);
        const int r1 = r0 + 8;
        const float bv0 = bias[r0], bv1 = bias[r1];
        #pragma unroll
        for (int nt = 0; nt < 4; nt++) {
            float2 v0, v1;
            v0.x = acc[mt][nt][0] + bv0;
            v0.y = acc[mt][nt][1] + bv0;
            v1.x = acc[mt][nt][2] + bv1;
            v1.y = acc[mt][nt][3] + bv1;
            *(float2*)&C[(size_t)r0 * N + col0 + nt * 8] = v0;
            *(float2*)&C[(size_t)r1 * N + col0 + nt * 8] = v1;
        }
    }
}

// ---------------- HMMA fused attention (R10) — bf16 hi/lo epilogue ----------
#define AS_QHI 0
#define AS_QLO 33792
#define AS_KHI 67584
#define AS_KLO 84480
#define AS_VHI 101376
#define AS_VLO 118272
#define AS_WHI 135168
#define AS_WLO 176128
#define AS_TOTAL 217088

__global__ __launch_bounds__(256) void attn_mma_kernel(
    const __nv_bfloat16* __restrict__ qt_hi, const __nv_bfloat16* __restrict__ qt_lo,
    __nv_bfloat16* __restrict__ out_hi, __nv_bfloat16* __restrict__ out_lo)
{
    extern __shared__ char sm[];
    const uint32_t sb = smem_u32(sm);
    const int tid = threadIdx.x, lane = tid & 31, wid = tid >> 5;
    const int wq = wid >> 1, w2 = wid & 1;
    const int qr0 = wq * 16;
    const int b = blockIdx.y, qbase = blockIdx.x * 64;
    const __nv_bfloat16* qth = qt_hi + (size_t)b * HW * DQKV;
    const __nv_bfloat16* qtl = qt_lo + (size_t)b * HW * DQKV;

    const int ar  = (lane & 7) + ((lane >> 3) & 1) * 8;
    const int ak  = ((lane >> 3) >> 1) * 8;
    const int br_ = (lane & 7);
    const int bk  = ((lane >> 3) & 1) * 8;

    // ---- prologue: Q + K0 (group 1), V0 (group 2) ----
    for (int i = tid; i < 2048; i += 256) {
        const int r = i >> 5, c = i & 31;
        const size_t so = (size_t)(qbase + r) * DQKV + c * 8;
        CP_ASYNC16(sb + AS_QHI + r * 528 + c * 16, qth + so);
        CP_ASYNC16(sb + AS_QLO + r * 528 + c * 16, qtl + so);
    }
    for (int i = tid; i < 1024; i += 256) {
        const int r = i >> 5, c = i & 31;
        const size_t so = (size_t)r * DQKV + 256 + c * 8;
        CP_ASYNC16(sb + AS_KHI + r * 528 + c * 16, qth + so);
        CP_ASYNC16(sb + AS_KLO + r * 528 + c * 16, qtl + so);
    }
    CP_COMMIT();
    for (int i = tid; i < 1024; i += 256) {
        const int r = i >> 5, c = i & 31;
        const size_t so = (size_t)r * DQKV + 512 + c * 8;
        CP_ASYNC16(sb + AS_VHI + r * 528 + c * 16, qth + so);
        CP_ASYNC16(sb + AS_VLO + r * 528 + c * 16, qtl + so);
    }
    CP_COMMIT();

    float acc[4][4][4] = {};

    for (int it = 0; it < 32; it++) {
        CP_WAIT1();           // K_it (and Q) arrived; V_it may be in flight
        __syncthreads();

        // ---- logits: warp tile 16q x 16k (k-half w2), all 8 heads ----
        float lg[8][2][4] = {};
        #pragma unroll
        for (int h = 0; h < 8; h++) {
            #pragma unroll
            for (int ks = 0; ks < 2; ks++) {
                const int dco = h * 32 + ks * 16;
                uint32_t aH[4], aL[4];
                const uint32_t aoff = (uint32_t)((qr0 + ar) * 528 + (dco + ak) * 2);
                LDSM_X4(aH[0], aH[1], aH[2], aH[3], sb + AS_QHI + aoff);
                LDSM_X4(aL[0], aL[1], aL[2], aL[3], sb + AS_QLO + aoff);
                #pragma unroll
                for (int t = 0; t < 2; t++) {
                    uint32_t bH[2], bL[2];
                    const uint32_t boff = (uint32_t)((w2 * 16 + t * 8 + br_) * 528 +
                                                     (dco + bk) * 2);
                    LDSM_X2(bH[0], bH[1], sb + AS_KHI + boff);
                    LDSM_X2(bL[0], bL[1], sb + AS_KLO + boff);
                    mma_bf16(lg[h][t], aH, bH);
                    mma_bf16(lg[h][t], aH, bL);
                    mma_bf16(lg[h][t], aL, bH);
                }
            }
        }
        __syncthreads();      // all warps done reading K_it

        // prefetch K_{it+1} into the (now free) K buffer
        if (it < 31) {
            const int kt = (it + 1) * 32;
            for (int i = tid; i < 1024; i += 256) {
                const int r = i >> 5, c = i & 31;
                const size_t so = (size_t)(kt + r) * DQKV + 256 + c * 8;
                CP_ASYNC16(sb + AS_KHI + r * 528 + c * 16, qth + so);
                CP_ASYNC16(sb + AS_KLO + r * 528 + c * 16, qtl + so);
            }
            CP_COMMIT();
        }

        // ---- head-softmax (thread-local) + weight store (bf16 hi/lo) ----
        #pragma unroll
        for (int t = 0; t < 2; t++) {
            #pragma unroll
            for (int p = 0; p < 2; p++) {
                float e0[8], e1[8];
                float s0 = 0.0f, s1 = 0.0f;
                #pragma unroll
                for (int h = 0; h < 8; h++) {
                    e0[h] = fast_exp(lg[h][t][p ? 2 : 0]);
                    e1[h] = fast_exp(lg[h][t][p ? 3 : 1]);
                    s0 += e0[h]; s1 += e1[h];
                }
                const float i0 = 1.0f / s0, i1 = 1.0f / s1;
                const int q = qr0 + (lane >> 2) + p * 8;
                const int k = w2 * 16 + t * 8 + (lane & 3) * 2;
                #pragma unroll
                for (int h = 0; h < 8; h++) {
                    const float wa = e0[h] * i0, wb = e1[h] * i1;
                    __nv_bfloat162 hh = __floats2bfloat162_rn(wa, wb);
                    __nv_bfloat162 ll = __floats2bfloat162_rn(wa - __bfloat162float(hh.x),
                                                              wb - __bfloat162float(hh.y));
                    const uint32_t off = (uint32_t)((h * 64 + q) * 80 + k * 2);
                    *(__nv_bfloat162*)(sm + AS_WHI + off) = hh;
                    *(__nv_bfloat162*)(sm + AS_WLO + off) = ll;
                }
            }
        }
        if (it < 31) { CP_WAIT1(); } else { CP_WAIT0(); }   // V_it arrived
        __syncthreads();                                    // W visible

        // ---- AV: warp owns 16q x 128d (heads w2*4..+3); V via ldmatrix.trans
        #pragma unroll
        for (int h4 = 0; h4 < 4; h4++) {
            const int habs = w2 * 4 + h4;
            #pragma unroll
            for (int ks = 0; ks < 2; ks++) {
                uint32_t wH[4], wL[4];
                const uint32_t aoff = (uint32_t)((habs * 64 + qr0 + ar) * 80 +
                                                 (ks * 16 + ak) * 2);
                LDSM_X4(wH[0], wH[1], wH[2], wH[3], sb + AS_WHI + aoff);
                LDSM_X4(wL[0], wL[1], wL[2], wL[3], sb + AS_WLO + aoff);
                #pragma unroll
                for (int nt = 0; nt < 4; nt++) {
                    uint32_t vH[2], vL[2];
                    const uint32_t boff = (uint32_t)((ks * 16 + ar) * 528 +
                                                     (habs * 32 + nt * 8) * 2);
                    LDSM_X2T(vH[0], vH[1], sb + AS_VHI + boff);
                    LDSM_X2T(vL[0], vL[1], sb + AS_VLO + boff);
                    mma_bf16(acc[h4][nt], wH, vH);
                    mma_bf16(acc[h4][nt], wH, vL);
                    mma_bf16(acc[h4][nt], wL, vH);
                }
            }
        }
        __syncthreads();      // V_it and W consumed

        // prefetch V_{it+1}
        if (it < 31) {
            const int kt = (it + 1) * 32;
            for (int i = tid; i < 1024; i += 256) {
                const int r = i >> 5, c = i & 31;
                const size_t so = (size_t)(kt + r) * DQKV + 512 + c * 8;
                CP_ASYNC16(sb + AS_VHI + r * 528 + c * 16, qth + so);
                CP_ASYNC16(sb + AS_VLO + r * 528 + c * 16, qtl + so);
            }
            CP_COMMIT();
        }
    }

    // ---- epilogue: ref-reshape layout, bf16 hi/lo (same values as fp32+split)
    __nv_bfloat16* ah = out_hi + (size_t)b * DVDIM * HW;
    __nv_bfloat16* al = out_lo + (size_t)b * DVDIM * HW;
    #pragma unroll
    for (int h4 = 0; h4 < 4; h4++) {
        const int habs = w2 * 4 + h4;
        #pragma unroll
        for (int nt = 0; nt < 4; nt++) {
            const int q0g = qbase + qr0 + (lane >> 2);
            const int q1g = q0g + 8;
            const int d   = nt * 8 + (lane & 3) * 2;
            const int ch0 = habs * 32 + (q0g >> 5), sp0 = (q0g & 31) * 32 + d;
            const int ch1 = habs * 32 + (q1g >> 5), sp1 = (q1g & 31) * 32 + d;
            const float v00 = acc[h4][nt][0], v01 = acc[h4][nt][1];
            const float v10 = acc[h4][nt][2], v11 = acc[h4][nt][3];
            __nv_bfloat162 h0 = __floats2bfloat162_rn(v00, v01);
            __nv_bfloat162 l0 = __floats2bfloat162_rn(v00 - __bfloat162float(h0.x),
                                                      v01 - __bfloat162float(h0.y));
            __nv_bfloat162 h1 = __floats2bfloat162_rn(v10, v11);
            __nv_bfloat162 l1 = __floats2bfloat162_rn(v10 - __bfloat162float(h1.x),
                                                      v11 - __bfloat162float(h1.y));
            *(__nv_bfloat162*)&ah[(size_t)ch0 * HW + sp0] = h0;
            *(__nv_bfloat162*)&al[(size_t)ch0 * HW + sp0] = l0;
            *(__nv_bfloat162*)&ah[(size_t)ch1 * HW + sp1] = h1;
            *(__nv_bfloat162*)&al[(size_t)ch1 * HW + sp1] = l1;
        }
    }
}

// ---------------------------------------------------------------------------
extern "C" void kernel_launch(void* const* d_in, const int* in_sizes, int n_in,
                              void* d_out, int out_size)
{
    const float* x      = (const float*)d_in[0];
    const float* w_qkv  = (const float*)d_in[1];
    const float* b_qkv  = (const float*)d_in[2];
    const float* w_attn = (const float*)d_in[3];
    const float* b_attn = (const float*)d_in[4];
    float* out = (float*)d_out;

    __nv_bfloat16 *qth, *qtl, *wqh, *wql, *wah, *wal, *xth, *xtl, *ath, *atl;
    cudaGetSymbolAddress((void**)&qth, g_qt_hi);
    cudaGetSymbolAddress((void**)&qtl, g_qt_lo);
    cudaGetSymbolAddress((void**)&wqh, g_wqkv_hi);
    cudaGetSymbolAddress((void**)&wql, g_wqkv_lo);
    cudaGetSymbolAddress((void**)&wah, g_wattn_hi);
    cudaGetSymbolAddress((void**)&wal, g_wattn_lo);
    cudaGetSymbolAddress((void**)&xth, g_xt_hi);
    cudaGetSymbolAddress((void**)&xtl, g_xt_lo);
    cudaGetSymbolAddress((void**)&ath, g_at_hi);
    cudaGetSymbolAddress((void**)&atl, g_at_lo);

    cudaFuncSetAttribute(gemm_mma<CIN, true, true>,
                         cudaFuncAttributeMaxDynamicSharedMemorySize, GM_SMEM);
    cudaFuncSetAttribute(gemm3_bt,
                         cudaFuncAttributeMaxDynamicSharedMemorySize, G3_SMEM);
    cudaFuncSetAttribute(attn_mma_kernel,
                         cudaFuncAttributeMaxDynamicSharedMemorySize, AS_TOTAL);

    // 0) precision-split weights; transpose+split x
    split_kernel<<<(DQKV * CIN + 255) / 256, 256>>>(w_qkv, wqh, wql, DQKV * CIN);
    split_kernel<<<(COUT * DVDIM + 255) / 256, 256>>>(w_attn, wah, wal, COUT * DVDIM);
    {
        dim3 grid(HW / 32, CIN / 32, BATCH);
        tsplit_kernel<<<grid, dim3(32, 8)>>>(x, xth, xtl, CIN, HW);
    }

    // 1) QKV projection TRANSPOSED, bf16 hi/lo output (+colbias, Q cols scaled)
    {
        dim3 grid(DQKV / 128, HW / 128, BATCH); // (6, 8, 8)
        gemm_mma<CIN, true, true><<<grid, 256, GM_SMEM>>>(
            xth, xtl, wqh, wql, b_qkv, nullptr, qth, qtl,
            HW, DQKV, (size_t)HW * CIN, 0, 256, 0.17677669529663687f);
    }

    // 2) fused HMMA attention -> bf16 hi/lo in ref-reshape [c][s] layout
    {
        dim3 grid(HW / 64, BATCH); // (16, 8)
        attn_mma_kernel<<<grid, 256, AS_TOTAL>>>(qth, qtl, ath, atl);
    }

    // 3) output projection, B consumed in [k][n] layout via trans-ldmatrix
    {
        dim3 grid(HW / 128, COUT / 128, BATCH); // (8, 4, 8)
        gemm3_bt<<<grid, 256, G3_SMEM>>>(wah, wal, ath, atl, b_attn, out);
    }
}

// round 16
// speedup vs baseline: 1.1206x; 1.0684x over previous
#include <cuda_runtime.h>
#include <cuda_bf16.h>
#include <cuda_fp16.h>
#include <cstdint>
#include <math.h>

#define BATCH 8
#define CIN   512
#define HW    1024
#define DQKV  768
#define DVDIM 256
#define COUT  512

// ---------------- scratch (static device globals; allocation-free rule) ----
__device__ __nv_bfloat16 g_qt_hi[(size_t)BATCH * HW * DQKV];  // 12 MB [b][s][o] qkvT hi
__device__ __nv_bfloat16 g_qt_lo[(size_t)BATCH * HW * DQKV];  // 12 MB [b][s][o] qkvT lo
__device__ __half        g_wqkv_f16[DQKV * CIN];              // w_qkv single f16
__device__ __nv_bfloat16 g_wattn_hi[COUT * DVDIM], g_wattn_lo[COUT * DVDIM];
__device__ __half        g_xf_hi[(size_t)BATCH * HW * CIN], g_xf_lo[(size_t)BATCH * HW * CIN];     // [b][s][c] f16
__device__ __nv_bfloat16 g_at_hi[(size_t)BATCH * DVDIM * HW], g_at_lo[(size_t)BATCH * DVDIM * HW]; // [b][c][s] ref-reshape

// ---------------- helpers ---------------------------------------------------
__device__ __forceinline__ uint32_t smem_u32(const void* p) {
    uint32_t a;
    asm("{ .reg .u64 t; cvta.to.shared.u64 t, %1; cvt.u32.u64 %0, t; }" : "=r"(a) : "l"(p));
    return a;
}

#define LDSM_X4(r0, r1, r2, r3, addr)                                           \
    asm volatile("ldmatrix.sync.aligned.m8n8.x4.shared.b16 {%0,%1,%2,%3}, [%4];"\
                 : "=r"(r0), "=r"(r1), "=r"(r2), "=r"(r3) : "r"(addr))
#define LDSM_X2(r0, r1, addr)                                                   \
    asm volatile("ldmatrix.sync.aligned.m8n8.x2.shared.b16 {%0,%1}, [%2];"      \
                 : "=r"(r0), "=r"(r1) : "r"(addr))
#define LDSM_X2T(r0, r1, addr)                                                  \
    asm volatile("ldmatrix.sync.aligned.m8n8.x2.trans.shared.b16 {%0,%1}, [%2];"\
                 : "=r"(r0), "=r"(r1) : "r"(addr))

#define CP_ASYNC16(dst, src)                                                    \
    asm volatile("cp.async.cg.shared.global [%0], [%1], 16;"                    \
                 :: "r"(dst), "l"(src))
#define CP_COMMIT() asm volatile("cp.async.commit_group;" ::: "memory")
#define CP_WAIT1()  asm volatile("cp.async.wait_group 1;" ::: "memory")
#define CP_WAIT0()  asm volatile("cp.async.wait_group 0;" ::: "memory")

__device__ __forceinline__ void mma_bf16(float* c, const uint32_t* a, const uint32_t* b) {
    asm volatile("mma.sync.aligned.m16n8k16.row.col.f32.bf16.bf16.f32 "
                 "{%0,%1,%2,%3}, {%4,%5,%6,%7}, {%8,%9}, {%0,%1,%2,%3};"
                 : "+f"(c[0]), "+f"(c[1]), "+f"(c[2]), "+f"(c[3])
                 : "r"(a[0]), "r"(a[1]), "r"(a[2]), "r"(a[3]), "r"(b[0]), "r"(b[1]));
}
__device__ __forceinline__ void mma_f16(float* c, const uint32_t* a, const uint32_t* b) {
    asm volatile("mma.sync.aligned.m16n8k16.row.col.f32.f16.f16.f32 "
                 "{%0,%1,%2,%3}, {%4,%5,%6,%7}, {%8,%9}, {%0,%1,%2,%3};"
                 : "+f"(c[0]), "+f"(c[1]), "+f"(c[2]), "+f"(c[3])
                 : "r"(a[0]), "r"(a[1]), "r"(a[2]), "r"(a[3]), "r"(b[0]), "r"(b[1]));
}

// FMA-pipe exp (no MUFU), |rel err| ~ 3e-7. Logits are tiny (sigma~0.2).
__device__ __forceinline__ float fast_exp(float x) {
    const float t  = x * 1.442695041f;
    const float tm = t + 12582912.0f;
    const int   k  = __float_as_int(tm) - 0x4b400000;
    const float f  = t - (tm - 12582912.0f);
    float p = 1.33336498e-3f;
    p = fmaf(p, f, 9.81094252e-3f);
    p = fmaf(p, f, 5.55036691e-2f);
    p = fmaf(p, f, 2.40226597e-1f);
    p = fmaf(p, f, 6.93147182e-1f);
    p = fmaf(p, f, 1.0f);
    return __int_as_float(__float_as_int(p) + (k << 23));
}

// ---------------- conversion kernels ---------------------------------------
// bf16 hi/lo split (for w_attn; GEMM3 path unchanged)
__global__ void split_kernel(const float* __restrict__ w,
                             __nv_bfloat16* __restrict__ hi,
                             __nv_bfloat16* __restrict__ lo, int n) {
    int i = blockIdx.x * 256 + threadIdx.x;
    if (i < n) {
        float v = w[i];
        __nv_bfloat16 h = __float2bfloat16(v);
        hi[i] = h;
        lo[i] = __float2bfloat16(v - __bfloat162float(h));
    }
}

// single f16 quantization (w_qkv)
__global__ void f16cast_kernel(const float* __restrict__ w,
                               __half* __restrict__ o, int n) {
    int i = blockIdx.x * 256 + threadIdx.x;
    if (i < n) o[i] = __float2half(w[i]);
}

// X[b][C][S] -> out[b][S][C] f16 hi/lo (transpose + split)
__global__ void tsplit_f16_kernel(const float* __restrict__ X,
                                  __half* __restrict__ hi,
                                  __half* __restrict__ lo, int C, int S) {
    __shared__ float t[32][33];
    const int b = blockIdx.z;
    const int c0 = blockIdx.y * 32, s0 = blockIdx.x * 32;
    const int tx = threadIdx.x, ty = threadIdx.y; // 32 x 8
    const float* Xb = X + (size_t)b * C * S;
    #pragma unroll
    for (int i = 0; i < 32; i += 8)
        t[ty + i][tx] = Xb[(size_t)(c0 + ty + i) * S + s0 + tx];
    __syncthreads();
    const size_t ob = (size_t)b * S * C;
    #pragma unroll
    for (int i = 0; i < 32; i += 8) {
        float v = t[tx][ty + i];
        __half h = __float2half(v);
        size_t idx = ob + (size_t)(s0 + ty + i) * C + c0 + tx;
        hi[idx] = h;
        lo[idx] = __float2half(v - __half2float(h));
    }
}

// ---------------- GEMM1: fp16 2-product, 128x128 tile, cp.async 2-stage -----
// qkvT[b][s][o] = sum_c x[s][c] * w[o][c] (+colbias, Q cols pre-scaled),
// output split to bf16 hi/lo. A = x f16 hi/lo, B = w single f16.
// smem/stage: Ahi 10240 + Alo 10240 + B 10240 = 30720; 2 stages = 61440.
#define G1_TA    (128 * 80)
#define G1_STAGE (3 * G1_TA)        // 30720
#define G1_SMEM  (2 * G1_STAGE)     // 61440

__global__ __launch_bounds__(256) void gemm1_f16(
    const __half* __restrict__ Ahi_g, const __half* __restrict__ Alo_g,
    const __half* __restrict__ Bf_g,
    const float* __restrict__ bias,
    __nv_bfloat16* __restrict__ Chi_all, __nv_bfloat16* __restrict__ Clo_all,
    int scale_limit, float scale)
{
    constexpr int K = CIN;     // 512
    constexpr int N = DQKV;    // 768 (output cols = o)
    extern __shared__ char smem[];
    const uint32_t sb = smem_u32(smem);

    const int tid  = threadIdx.x;
    const int wid  = tid >> 5;
    const int lane = tid & 31;
    const int wm = wid >> 2;       // 0..1 -> 64-row band (s)
    const int wn = wid & 3;        // 0..3 -> 32-col band (o)
    const int b  = blockIdx.z, m0 = blockIdx.y * 128, n0 = blockIdx.x * 128;

    const __half* Ahi = Ahi_g + (size_t)b * HW * K + (size_t)m0 * K;
    const __half* Alo = Alo_g + (size_t)b * HW * K + (size_t)m0 * K;
    const __half* Bf  = Bf_g + (size_t)n0 * K;

    const int a_row  = wm * 64 + (lane & 7) + ((lane >> 3) & 1) * 8;
    const int a_koff = ((lane >> 3) >> 1) * 8;
    const int b_row  = wn * 32 + (lane & 7);
    const int b_koff = ((lane >> 3) & 1) * 8;

    float acc[4][4][4] = {};
    constexpr int NCH = K / 32;    // 16

    // copy plan: 1536 16B chunks/stage, 6 per thread.
    #pragma unroll
    for (int it = 0; it < 6; it++) {
        const int slot = it * 256 + tid;
        const int t  = slot >> 9;          // 0=Ahi,1=Alo,2=B
        const int in_ = slot & 511;
        const int r  = in_ >> 2;
        const int cg = in_ & 3;
        const __half* src = (t == 0 ? Ahi : (t == 1 ? Alo : Bf)) + (size_t)r * K + cg * 8;
        CP_ASYNC16(sb + t * G1_TA + r * 80 + cg * 16, src);
    }
    CP_COMMIT();

    for (int ch = 0; ch < NCH; ch++) {
        if (ch + 1 < NCH) {
            const uint32_t dstb = sb + ((ch + 1) & 1) * G1_STAGE;
            const int c0k = (ch + 1) * 32;
            #pragma unroll
            for (int it = 0; it < 6; it++) {
                const int slot = it * 256 + tid;
                const int t  = slot >> 9;
                const int in_ = slot & 511;
                const int r  = in_ >> 2;
                const int cg = in_ & 3;
                const __half* src = (t == 0 ? Ahi : (t == 1 ? Alo : Bf)) +
                                    (size_t)r * K + c0k + cg * 8;
                CP_ASYNC16(dstb + t * G1_TA + r * 80 + cg * 16, src);
            }
            CP_COMMIT();
            CP_WAIT1();
        } else {
            CP_WAIT0();
        }
        __syncthreads();

        const uint32_t st = sb + (ch & 1) * G1_STAGE;
        const uint32_t sAhi_u = st, sAlo_u = st + G1_TA, sB_u = st + 2 * G1_TA;

        #pragma unroll
        for (int ks = 0; ks < 2; ks++) {
            const int kb = ks * 16;
            uint32_t bf[4][2];
            #pragma unroll
            for (int nt = 0; nt < 4; nt++) {
                const uint32_t off = (uint32_t)((b_row + nt * 8) * 80 +
                                                (kb + b_koff) * 2);
                LDSM_X2(bf[nt][0], bf[nt][1], sB_u + off);
            }
            #pragma unroll
            for (int mt = 0; mt < 4; mt++) {
                const uint32_t off = (uint32_t)((a_row + mt * 16) * 80 +
                                                (kb + a_koff) * 2);
                uint32_t ah[4], al[4];
                LDSM_X4(ah[0], ah[1], ah[2], ah[3], sAhi_u + off);
                LDSM_X4(al[0], al[1], al[2], al[3], sAlo_u + off);
                #pragma unroll
                for (int nt = 0; nt < 4; nt++) {
                    mma_f16(acc[mt][nt], ah, bf[nt]);
                    mma_f16(acc[mt][nt], al, bf[nt]);
                }
            }
        }
        __syncthreads();
    }

    // epilogue: column bias + Q-col scale, output bf16 hi/lo
    __nv_bfloat16* Chi = Chi_all + (size_t)b * HW * N;
    __nv_bfloat16* Clo = Clo_all + (size_t)b * HW * N;
    const int col0 = n0 + wn * 32 + (lane & 3) * 2;
    #pragma unroll
    for (int mt = 0; mt < 4; mt++) {
        const int r0 = m0 + wm * 64 + mt * 16 + (lane >> 2);
        const int r1 = r0 + 8;
        #pragma unroll
        for (int nt = 0; nt < 4; nt++) {
            const int cx = col0 + nt * 8, cy = cx + 1;
            const float bvx = bias[cx], bvy = bias[cy];
            const float scx = (cx < scale_limit) ? scale : 1.0f;
            const float scy = (cy < scale_limit) ? scale : 1.0f;
            const float v0x = (acc[mt][nt][0] + bvx) * scx;
            const float v0y = (acc[mt][nt][1] + bvy) * scy;
            const float v1x = (acc[mt][nt][2] + bvx) * scx;
            const float v1y = (acc[mt][nt][3] + bvy) * scy;
            __nv_bfloat162 h0 = __floats2bfloat162_rn(v0x, v0y);
            __nv_bfloat162 l0 = __floats2bfloat162_rn(v0x - __bfloat162float(h0.x),
                                                      v0y - __bfloat162float(h0.y));
            __nv_bfloat162 h1 = __floats2bfloat162_rn(v1x, v1y);
            __nv_bfloat162 l1 = __floats2bfloat162_rn(v1x - __bfloat162float(h1.x),
                                                      v1y - __bfloat162float(h1.y));
            *(__nv_bfloat162*)&Chi[(size_t)r0 * N + cx] = h0;
            *(__nv_bfloat162*)&Clo[(size_t)r0 * N + cx] = l0;
            *(__nv_bfloat162*)&Chi[(size_t)r1 * N + cx] = h1;
            *(__nv_bfloat162*)&Clo[(size_t)r1 * N + cx] = l1;
        }
    }
}

// ---------------- GEMM3: B in [k][n] layout (trans ldmatrix), row bias ------
#define G3_SA   (128 * 80)          // 10240 B per A tile
#define G3_SB   (32 * 272)          // 8704 B per B tile
#define G3_STAGE (2 * G3_SA + 2 * G3_SB)   // 37888 B
#define G3_SMEM  (2 * G3_STAGE)            // 75776 B

__global__ __launch_bounds__(256) void gemm3_bt(
    const __nv_bfloat16* __restrict__ Ahi_g, const __nv_bfloat16* __restrict__ Alo_g,
    const __nv_bfloat16* __restrict__ Bhi_g, const __nv_bfloat16* __restrict__ Blo_g,
    const float* __restrict__ bias, float* __restrict__ C_all)
{
    constexpr int K = DVDIM;     // 256
    constexpr int N = HW;        // 1024
    constexpr int M = COUT;      // 512
    extern __shared__ char smem[];
    const uint32_t sb = smem_u32(smem);

    const int tid  = threadIdx.x;
    const int wid  = tid >> 5;
    const int lane = tid & 31;
    const int wm = wid >> 2;
    const int wn = wid & 3;
    const int b  = blockIdx.z, m0 = blockIdx.y * 128, n0 = blockIdx.x * 128;

    const __nv_bfloat16* Ahi = Ahi_g + (size_t)m0 * K;
    const __nv_bfloat16* Alo = Alo_g + (size_t)m0 * K;
    const __nv_bfloat16* Bhi = Bhi_g + (size_t)b * K * N + n0;
    const __nv_bfloat16* Blo = Blo_g + (size_t)b * K * N + n0;
    float* C = C_all + (size_t)b * M * N;

    const int a_row  = wm * 64 + (lane & 7) + ((lane >> 3) & 1) * 8;
    const int a_koff = ((lane >> 3) >> 1) * 8;
    const int tb_row = (lane & 7) + ((lane >> 3) & 1) * 8;

    float acc[4][4][4] = {};
    constexpr int NCH = K / 32;   // 8

    #pragma unroll
    for (int it = 0; it < 8; it++) {
        const int slot = it * 256 + tid;
        if (slot < 1024) {
            const int hl = slot >> 9, in_ = slot & 511;
            const int r = in_ >> 2, cg = in_ & 3;
            CP_ASYNC16(sb + hl * G3_SA + r * 80 + cg * 16,
                       (hl ? Alo : Ahi) + (size_t)r * K + cg * 8);
        } else {
            const int s2 = slot - 1024;
            const int hl = s2 >> 9, in_ = s2 & 511;
            const int r = in_ >> 4, cg = in_ & 15;
            CP_ASYNC16(sb + 2 * G3_SA + hl * G3_SB + r * 272 + cg * 16,
                       (hl ? Blo : Bhi) + (size_t)r * N + cg * 8);
        }
    }
    CP_COMMIT();

    for (int ch = 0; ch < NCH; ch++) {
        if (ch + 1 < NCH) {
            const uint32_t dstb = sb + ((ch + 1) & 1) * G3_STAGE;
            const int c0k = (ch + 1) * 32;
            #pragma unroll
            for (int it = 0; it < 8; it++) {
                const int slot = it * 256 + tid;
                if (slot < 1024) {
                    const int hl = slot >> 9, in_ = slot & 511;
                    const int r = in_ >> 2, cg = in_ & 3;
                    CP_ASYNC16(dstb + hl * G3_SA + r * 80 + cg * 16,
                               (hl ? Alo : Ahi) + (size_t)r * K + c0k + cg * 8);
                } else {
                    const int s2 = slot - 1024;
                    const int hl = s2 >> 9, in_ = s2 & 511;
                    const int r = in_ >> 4, cg = in_ & 15;
                    CP_ASYNC16(dstb + 2 * G3_SA + hl * G3_SB + r * 272 + cg * 16,
                               (hl ? Blo : Bhi) + (size_t)(c0k + r) * N + cg * 8);
                }
            }
            CP_COMMIT();
            CP_WAIT1();
        } else {
            CP_WAIT0();
        }
        __syncthreads();

        const uint32_t st = sb + (ch & 1) * G3_STAGE;
        const uint32_t sAhi_u = st, sAlo_u = st + G3_SA;
        const uint32_t sBhi_u = st + 2 * G3_SA, sBlo_u = st + 2 * G3_SA + G3_SB;

        #pragma unroll
        for (int ks = 0; ks < 2; ks++) {
            const int kb = ks * 16;
            uint32_t bh[4][2], bl[4][2];
            #pragma unroll
            for (int nt = 0; nt < 4; nt++) {
                const uint32_t off = (uint32_t)((kb + tb_row) * 272 +
                                                (wn * 32 + nt * 8) * 2);
                LDSM_X2T(bh[nt][0], bh[nt][1], sBhi_u + off);
                LDSM_X2T(bl[nt][0], bl[nt][1], sBlo_u + off);
            }
            #pragma unroll
            for (int mt = 0; mt < 4; mt++) {
                const uint32_t off = (uint32_t)((a_row + mt * 16) * 80 +
                                                (kb + a_koff) * 2);
                uint32_t ah[4], al[4];
                LDSM_X4(ah[0], ah[1], ah[2], ah[3], sAhi_u + off);
                LDSM_X4(al[0], al[1], al[2], al[3], sAlo_u + off);
                #pragma unroll
                for (int nt = 0; nt < 4; nt++) {
                    mma_bf16(acc[mt][nt], ah, bh[nt]);
                    mma_bf16(acc[mt][nt], ah, bl[nt]);
                    mma_bf16(acc[mt][nt], al, bh[nt]);
                }
            }
        }
        __syncthreads();
    }

    const int col0 = n0 + wn * 32 + (lane & 3) * 2;
    #pragma unroll
    for (int mt = 0; mt < 4; mt++) {
        const int r0 = m0 + wm * 64 + mt * 16 + (lane >> 2);
        const int r1 = r0 + 8;
        const float bv0 = bias[r0], bv1 = bias[r1];
        #pragma unroll
        for (int nt = 0; nt < 4; nt++) {
            float2 v0, v1;
            v0.x = acc[mt][nt][0] + bv0;
            v0.y = acc[mt][nt][1] + bv0;
            v1.x = acc[mt][nt][2] + bv1;
            v1.y = acc[mt][nt][3] + bv1;
            *(float2*)&C[(size_t)r0 * N + col0 + nt * 8] = v0;
            *(float2*)&C[(size_t)r1 * N + col0 + nt * 8] = v1;
        }
    }
}

// ---------------- HMMA fused attention (R10) — bf16 hi/lo epilogue ----------
#define AS_QHI 0
#define AS_QLO 33792
#define AS_KHI 67584
#define AS_KLO 84480
#define AS_VHI 101376
#define AS_VLO 118272
#define AS_WHI 135168
#define AS_WLO 176128
#define AS_TOTAL 217088

__global__ __launch_bounds__(256) void attn_mma_kernel(
    const __nv_bfloat16* __restrict__ qt_hi, const __nv_bfloat16* __restrict__ qt_lo,
    __nv_bfloat16* __restrict__ out_hi, __nv_bfloat16* __restrict__ out_lo)
{
    extern __shared__ char sm[];
    const uint32_t sb = smem_u32(sm);
    const int tid = threadIdx.x, lane = tid & 31, wid = tid >> 5;
    const int wq = wid >> 1, w2 = wid & 1;
    const int qr0 = wq * 16;
    const int b = blockIdx.y, qbase = blockIdx.x * 64;
    const __nv_bfloat16* qth = qt_hi + (size_t)b * HW * DQKV;
    const __nv_bfloat16* qtl = qt_lo + (size_t)b * HW * DQKV;

    const int ar  = (lane & 7) + ((lane >> 3) & 1) * 8;
    const int ak  = ((lane >> 3) >> 1) * 8;
    const int br_ = (lane & 7);
    const int bk  = ((lane >> 3) & 1) * 8;

    // ---- prologue: Q + K0 (group 1), V0 (group 2) ----
    for (int i = tid; i < 2048; i += 256) {
        const int r = i >> 5, c = i & 31;
        const size_t so = (size_t)(qbase + r) * DQKV + c * 8;
        CP_ASYNC16(sb + AS_QHI + r * 528 + c * 16, qth + so);
        CP_ASYNC16(sb + AS_QLO + r * 528 + c * 16, qtl + so);
    }
    for (int i = tid; i < 1024; i += 256) {
        const int r = i >> 5, c = i & 31;
        const size_t so = (size_t)r * DQKV + 256 + c * 8;
        CP_ASYNC16(sb + AS_KHI + r * 528 + c * 16, qth + so);
        CP_ASYNC16(sb + AS_KLO + r * 528 + c * 16, qtl + so);
    }
    CP_COMMIT();
    for (int i = tid; i < 1024; i += 256) {
        const int r = i >> 5, c = i & 31;
        const size_t so = (size_t)r * DQKV + 512 + c * 8;
        CP_ASYNC16(sb + AS_VHI + r * 528 + c * 16, qth + so);
        CP_ASYNC16(sb + AS_VLO + r * 528 + c * 16, qtl + so);
    }
    CP_COMMIT();

    float acc[4][4][4] = {};

    for (int it = 0; it < 32; it++) {
        CP_WAIT1();           // K_it (and Q) arrived; V_it may be in flight
        __syncthreads();

        // ---- logits: warp tile 16q x 16k (k-half w2), all 8 heads ----
        float lg[8][2][4] = {};
        #pragma unroll
        for (int h = 0; h < 8; h++) {
            #pragma unroll
            for (int ks = 0; ks < 2; ks++) {
                const int dco = h * 32 + ks * 16;
                uint32_t aH[4], aL[4];
                const uint32_t aoff = (uint32_t)((qr0 + ar) * 528 + (dco + ak) * 2);
                LDSM_X4(aH[0], aH[1], aH[2], aH[3], sb + AS_QHI + aoff);
                LDSM_X4(aL[0], aL[1], aL[2], aL[3], sb + AS_QLO + aoff);
                #pragma unroll
                for (int t = 0; t < 2; t++) {
                    uint32_t bH[2], bL[2];
                    const uint32_t boff = (uint32_t)((w2 * 16 + t * 8 + br_) * 528 +
                                                     (dco + bk) * 2);
                    LDSM_X2(bH[0], bH[1], sb + AS_KHI + boff);
                    LDSM_X2(bL[0], bL[1], sb + AS_KLO + boff);
                    mma_bf16(lg[h][t], aH, bH);
                    mma_bf16(lg[h][t], aH, bL);
                    mma_bf16(lg[h][t], aL, bH);
                }
            }
        }
        __syncthreads();      // all warps done reading K_it

        // prefetch K_{it+1} into the (now free) K buffer
        if (it < 31) {
            const int kt = (it + 1) * 32;
            for (int i = tid; i < 1024; i += 256) {
                const int r = i >> 5, c = i & 31;
                const size_t so = (size_t)(kt + r) * DQKV + 256 + c * 8;
                CP_ASYNC16(sb + AS_KHI + r * 528 + c * 16, qth + so);
                CP_ASYNC16(sb + AS_KLO + r * 528 + c * 16, qtl + so);
            }
            CP_COMMIT();
        }

        // ---- head-softmax (thread-local) + weight store (bf16 hi/lo) ----
        #pragma unroll
        for (int t = 0; t < 2; t++) {
            #pragma unroll
            for (int p = 0; p < 2; p++) {
                float e0[8], e1[8];
                float s0 = 0.0f, s1 = 0.0f;
                #pragma unroll
                for (int h = 0; h < 8; h++) {
                    e0[h] = fast_exp(lg[h][t][p ? 2 : 0]);
                    e1[h] = fast_exp(lg[h][t][p ? 3 : 1]);
                    s0 += e0[h]; s1 += e1[h];
                }
                const float i0 = 1.0f / s0, i1 = 1.0f / s1;
                const int q = qr0 + (lane >> 2) + p * 8;
                const int k = w2 * 16 + t * 8 + (lane & 3) * 2;
                #pragma unroll
                for (int h = 0; h < 8; h++) {
                    const float wa = e0[h] * i0, wb = e1[h] * i1;
                    __nv_bfloat162 hh = __floats2bfloat162_rn(wa, wb);
                    __nv_bfloat162 ll = __floats2bfloat162_rn(wa - __bfloat162float(hh.x),
                                                              wb - __bfloat162float(hh.y));
                    const uint32_t off = (uint32_t)((h * 64 + q) * 80 + k * 2);
                    *(__nv_bfloat162*)(sm + AS_WHI + off) = hh;
                    *(__nv_bfloat162*)(sm + AS_WLO + off) = ll;
                }
            }
        }
        if (it < 31) { CP_WAIT1(); } else { CP_WAIT0(); }   // V_it arrived
        __syncthreads();                                    // W visible

        // ---- AV: warp owns 16q x 128d (heads w2*4..+3); V via ldmatrix.trans
        #pragma unroll
        for (int h4 = 0; h4 < 4; h4++) {
            const int habs = w2 * 4 + h4;
            #pragma unroll
            for (int ks = 0; ks < 2; ks++) {
                uint32_t wH[4], wL[4];
                const uint32_t aoff = (uint32_t)((habs * 64 + qr0 + ar) * 80 +
                                                 (ks * 16 + ak) * 2);
                LDSM_X4(wH[0], wH[1], wH[2], wH[3], sb + AS_WHI + aoff);
                LDSM_X4(wL[0], wL[1], wL[2], wL[3], sb + AS_WLO + aoff);
                #pragma unroll
                for (int nt = 0; nt < 4; nt++) {
                    uint32_t vH[2], vL[2];
                    const uint32_t boff = (uint32_t)((ks * 16 + ar) * 528 +
                                                     (habs * 32 + nt * 8) * 2);
                    LDSM_X2T(vH[0], vH[1], sb + AS_VHI + boff);
                    LDSM_X2T(vL[0], vL[1], sb + AS_VLO + boff);
                    mma_bf16(acc[h4][nt], wH, vH);
                    mma_bf16(acc[h4][nt], wH, vL);
                    mma_bf16(acc[h4][nt], wL, vH);
                }
            }
        }
        __syncthreads();      // V_it and W consumed

        // prefetch V_{it+1}
        if (it < 31) {
            const int kt = (it + 1) * 32;
            for (int i = tid; i < 1024; i += 256) {
                const int r = i >> 5, c = i & 31;
                const size_t so = (size_t)(kt + r) * DQKV + 512 + c * 8;
                CP_ASYNC16(sb + AS_VHI + r * 528 + c * 16, qth + so);
                CP_ASYNC16(sb + AS_VLO + r * 528 + c * 16, qtl + so);
            }
            CP_COMMIT();
        }
    }

    // ---- epilogue: ref-reshape layout, bf16 hi/lo ----
    __nv_bfloat16* ah = out_hi + (size_t)b * DVDIM * HW;
    __nv_bfloat16* al = out_lo + (size_t)b * DVDIM * HW;
    #pragma unroll
    for (int h4 = 0; h4 < 4; h4++) {
        const int habs = w2 * 4 + h4;
        #pragma unroll
        for (int nt = 0; nt < 4; nt++) {
            const int q0g = qbase + qr0 + (lane >> 2);
            const int q1g = q0g + 8;
            const int d   = nt * 8 + (lane & 3) * 2;
            const int ch0 = habs * 32 + (q0g >> 5), sp0 = (q0g & 31) * 32 + d;
            const int ch1 = habs * 32 + (q1g >> 5), sp1 = (q1g & 31) * 32 + d;
            const float v00 = acc[h4][nt][0], v01 = acc[h4][nt][1];
            const float v10 = acc[h4][nt][2], v11 = acc[h4][nt][3];
            __nv_bfloat162 h0 = __floats2bfloat162_rn(v00, v01);
            __nv_bfloat162 l0 = __floats2bfloat162_rn(v00 - __bfloat162float(h0.x),
                                                      v01 - __bfloat162float(h0.y));
            __nv_bfloat162 h1 = __floats2bfloat162_rn(v10, v11);
            __nv_bfloat162 l1 = __floats2bfloat162_rn(v10 - __bfloat162float(h1.x),
                                                      v11 - __bfloat162float(h1.y));
            *(__nv_bfloat162*)&ah[(size_t)ch0 * HW + sp0] = h0;
            *(__nv_bfloat162*)&al[(size_t)ch0 * HW + sp0] = l0;
            *(__nv_bfloat162*)&ah[(size_t)ch1 * HW + sp1] = h1;
            *(__nv_bfloat162*)&al[(size_t)ch1 * HW + sp1] = l1;
        }
    }
}

// ---------------------------------------------------------------------------
extern "C" void kernel_launch(void* const* d_in, const int* in_sizes, int n_in,
                              void* d_out, int out_size)
{
    const float* x      = (const float*)d_in[0];
    const float* w_qkv  = (const float*)d_in[1];
    const float* b_qkv  = (const float*)d_in[2];
    const float* w_attn = (const float*)d_in[3];
    const float* b_attn = (const float*)d_in[4];
    float* out = (float*)d_out;

    __nv_bfloat16 *qth, *qtl, *wah, *wal, *ath, *atl;
    __half *wqf, *xfh, *xfl;
    cudaGetSymbolAddress((void**)&qth, g_qt_hi);
    cudaGetSymbolAddress((void**)&qtl, g_qt_lo);
    cudaGetSymbolAddress((void**)&wqf, g_wqkv_f16);
    cudaGetSymbolAddress((void**)&wah, g_wattn_hi);
    cudaGetSymbolAddress((void**)&wal, g_wattn_lo);
    cudaGetSymbolAddress((void**)&xfh, g_xf_hi);
    cudaGetSymbolAddress((void**)&xfl, g_xf_lo);
    cudaGetSymbolAddress((void**)&ath, g_at_hi);
    cudaGetSymbolAddress((void**)&atl, g_at_lo);

    cudaFuncSetAttribute(gemm1_f16,
                         cudaFuncAttributeMaxDynamicSharedMemorySize, G1_SMEM);
    cudaFuncSetAttribute(gemm3_bt,
                         cudaFuncAttributeMaxDynamicSharedMemorySize, G3_SMEM);
    cudaFuncSetAttribute(attn_mma_kernel,
                         cudaFuncAttributeMaxDynamicSharedMemorySize, AS_TOTAL);

    // 0) w_qkv -> f16 single; w_attn -> bf16 hi/lo; x -> [b][s][c] f16 hi/lo
    f16cast_kernel<<<(DQKV * CIN + 255) / 256, 256>>>(w_qkv, wqf, DQKV * CIN);
    split_kernel<<<(COUT * DVDIM + 255) / 256, 256>>>(w_attn, wah, wal, COUT * DVDIM);
    {
        dim3 grid(HW / 32, CIN / 32, BATCH);
        tsplit_f16_kernel<<<grid, dim3(32, 8)>>>(x, xfh, xfl, CIN, HW);
    }

    // 1) QKV projection (fp16 2-product), bf16 hi/lo output, Q cols pre-scaled
    {
        dim3 grid(DQKV / 128, HW / 128, BATCH); // (6, 8, 8)
        gemm1_f16<<<grid, 256, G1_SMEM>>>(xfh, xfl, wqf, b_qkv, qth, qtl,
                                          256, 0.17677669529663687f);
    }

    // 2) fused HMMA attention -> bf16 hi/lo in ref-reshape [c][s] layout
    {
        dim3 grid(HW / 64, BATCH); // (16, 8)
        attn_mma_kernel<<<grid, 256, AS_TOTAL>>>(qth, qtl, ath, atl);
    }

    // 3) output projection, B consumed in [k][n] layout via trans-ldmatrix
    {
        dim3 grid(HW / 128, COUT / 128, BATCH); // (8, 4, 8)
        gemm3_bt<<<grid, 256, G3_SMEM>>>(wah, wal, ath, atl, b_attn, out);
    }
}